// round 7
// baseline (speedup 1.0000x reference)
#include <cuda_runtime.h>
#include <cstdint>

// Fixed shapes: pred/target = [4, 8192, 3] fp32
#define NB        4
#define NPTS      8192
#define THREADS   128
#define IPT       8                    // pred points per thread
#define I_PER_WARP (32 * IPT)          // 256
#define I_PER_CTA  (4 * I_PER_WARP)    // 1024
#define JT        512                  // target tile per CTA
#define ICH       (NPTS / I_PER_CTA)   // 8
#define JCH       (NPTS / JT)          // 16

// Partials (static device scratch — allowed)
__device__ float g_rmin[NB][JCH][NPTS];  // per (b,jch): min_{j in tile} dist^2/2, per pred i (2MB)
__device__ float g_cmin[NB][ICH][NPTS];  // per (b,ich): min_{i in chunk} dist^2/2, per tgt j (1MB)

// Symmetric fused cross kernel: computes each (i,j) pair ONCE, feeds both
// chamfer directions.  u = p.q - h_q ;  t = h_p - u = dist^2/2.
__global__ void __launch_bounds__(THREADS, 4)
chamfer_cross_kernel(const float* __restrict__ pred, const float* __restrict__ tgt) {
    __shared__ float4 sq[JT];        // (qx, qy, qz, -h_q)   8 KB
    __shared__ float  scol[4][JT];   // per-warp col mins    8 KB

    const int jch  = blockIdx.x;
    const int ich  = blockIdx.y;
    const int b    = blockIdx.z;
    const int tid  = threadIdx.x;
    const int w    = tid >> 5;
    const int lane = tid & 31;

    const float* P = pred + (size_t)b * NPTS * 3;
    const float* Q = tgt  + (size_t)b * NPTS * 3;

    // Stage target tile.
    for (int j = tid; j < JT; j += THREADS) {
        int gj = jch * JT + j;
        float x = Q[3 * gj + 0], y = Q[3 * gj + 1], z = Q[3 * gj + 2];
        float nh = -0.5f * fmaf(x, x, fmaf(y, y, z * z));
        sq[j] = make_float4(x, y, z, nh);
    }

    // Register-resident pred points.
    const int ib = ich * I_PER_CTA + w * I_PER_WARP + lane * IPT;
    float px[IPT], py[IPT], pz[IPT], hp[IPT], rmin[IPT];
#pragma unroll
    for (int k = 0; k < IPT; k++) {
        float x = P[3 * (ib + k) + 0];
        float y = P[3 * (ib + k) + 1];
        float z = P[3 * (ib + k) + 2];
        px[k] = x; py[k] = y; pz[k] = z;
        hp[k] = 0.5f * fmaf(x, x, fmaf(y, y, z * z));
        rmin[k] = __int_as_float(0x7f800000);   // +inf
    }
    __syncthreads();

#pragma unroll 2
    for (int j = 0; j < JT; j++) {
        float4 q = sq[j];            // LDS.128 broadcast
        float t[IPT];
#pragma unroll
        for (int k = 0; k < IPT; k++) {
            float u = fmaf(pz[k], q.z, fmaf(py[k], q.y, fmaf(px[k], q.x, q.w)));
            t[k] = fmaf(u, -1.0f, hp[k]);        // FFMA-imm (rt=1): dist^2/2
            rmin[k] = fminf(rmin[k], t[k]);      // dir0 (pred->tgt), alu pipe
        }
        // dir1 (tgt->pred): min over this thread's 8 i's, then warp min.
        float m = fminf(fminf(fminf(t[0], t[1]), fminf(t[2], t[3])),
                        fminf(fminf(t[4], t[5]), fminf(t[6], t[7])));
#pragma unroll
        for (int off = 16; off; off >>= 1)
            m = fminf(m, __shfl_xor_sync(0xffffffffu, m, off));
        if (lane == 0) scol[w][j] = m;           // each (w,j) written once
    }

    // Row partials out.
#pragma unroll
    for (int k = 0; k < IPT; k++)
        g_rmin[b][jch][ib + k] = rmin[k];

    __syncthreads();
    // Combine the 4 warps' col mins; col partials out.
    for (int j = tid; j < JT; j += THREADS) {
        float m = fminf(fminf(scol[0][j], scol[1][j]), fminf(scol[2][j], scol[3][j]));
        g_cmin[b][ich][jch * JT + j] = m;
    }
}

__global__ void zero_out_kernel(float* out) { *out = 0.0f; }

// Tail: combine chunk partials, mean over points, accumulate scalar.
__global__ void chamfer_tail_kernel(float* __restrict__ out) {
    __shared__ float red[256];
    const int b    = blockIdx.x;
    const int side = blockIdx.y;
    float sum = 0.0f;
    if (side == 0) {
        for (int i = threadIdx.x; i < NPTS; i += 256) {
            float m = g_rmin[b][0][i];
#pragma unroll
            for (int c = 1; c < JCH; c++) m = fminf(m, g_rmin[b][c][i]);
            sum += m;
        }
    } else {
        for (int j = threadIdx.x; j < NPTS; j += 256) {
            float m = g_cmin[b][0][j];
#pragma unroll
            for (int c = 1; c < ICH; c++) m = fminf(m, g_cmin[b][c][j]);
            sum += m;
        }
    }
    red[threadIdx.x] = sum;
    __syncthreads();
    for (int o = 128; o; o >>= 1) {
        if (threadIdx.x < o) red[threadIdx.x] += red[threadIdx.x + o];
        __syncthreads();
    }
    // stored values are dist^2/2 -> multiply by 2; mean over NB and NPTS.
    if (threadIdx.x == 0)
        atomicAdd(out, red[0] * (2.0f / ((float)NB * (float)NPTS)));
}

extern "C" void kernel_launch(void* const* d_in, const int* in_sizes, int n_in,
                              void* d_out, int out_size) {
    const float* pred = (const float*)d_in[0];
    const float* tgt  = (const float*)d_in[1];
    float* out = (float*)d_out;
    (void)in_sizes; (void)n_in; (void)out_size;

    zero_out_kernel<<<1, 1>>>(out);
    dim3 grid(JCH, ICH, NB);              // 16 x 8 x 4 = 512 CTAs, one wave
    chamfer_cross_kernel<<<grid, THREADS>>>(pred, tgt);
    dim3 tgrid(NB, 2);
    chamfer_tail_kernel<<<tgrid, 256>>>(out);
}

// round 9
// speedup vs baseline: 1.5415x; 1.5415x over previous
#include <cuda_runtime.h>
#include <cstdint>

// Fixed shapes: pred/target = [4, 8192, 3] fp32
#define NB        4
#define NPTS      8192
#define THREADS   128
#define IPT       8                    // pred points per thread
#define I_PER_CTA 1024                 // 4 warps * 32 lanes * IPT
#define JT        512                  // target tile per CTA
#define ICH       (NPTS / I_PER_CTA)   // 8
#define JCH       (NPTS / JT)          // 16
#define INF_BITS  0x7f800000

// Global min arrays as int bits (dist^2/2 >= 0 -> IEEE order == int order).
__device__ int g_rmin[NB * NPTS];   // 128 KB: per pred i, min over all j
__device__ int g_cmin[NB * NPTS];   // 128 KB: per tgt  j, min over all i

// Symmetric fused cross kernel: each (i,j) computed ONCE, feeds both directions.
//   u = p.q - h_q ;  t = h_p - u = dist^2/2
// Column mins use a systolic rotation: one SHFL per 256 pairs.
__global__ void __launch_bounds__(THREADS, 4)
chamfer_cross_kernel(const float* __restrict__ pred, const float* __restrict__ tgt) {
    __shared__ float4 sq[JT];        // (qx, qy, qz, -h_q)   8 KB
    __shared__ float  scol[4][JT];   // per-warp col mins    8 KB

    const int jch  = blockIdx.x;
    const int ich  = blockIdx.y;
    const int b    = blockIdx.z;
    const int tid  = threadIdx.x;
    const int w    = tid >> 5;
    const int lane = tid & 31;

    const float* P = pred + (size_t)b * NPTS * 3;
    const float* Q = tgt  + (size_t)b * NPTS * 3;

    // Stage target tile.
    for (int j = tid; j < JT; j += THREADS) {
        int gj = jch * JT + j;
        float x = Q[3 * gj + 0], y = Q[3 * gj + 1], z = Q[3 * gj + 2];
        float nh = -0.5f * fmaf(x, x, fmaf(y, y, z * z));
        sq[j] = make_float4(x, y, z, nh);
    }

    // Register-resident pred points for this lane.
    const int ib = ich * I_PER_CTA + w * (32 * IPT) + lane * IPT;
    float px[IPT], py[IPT], pz[IPT], hp[IPT], rmin[IPT];
#pragma unroll
    for (int k = 0; k < IPT; k++) {
        float x = P[3 * (ib + k) + 0];
        float y = P[3 * (ib + k) + 1];
        float z = P[3 * (ib + k) + 2];
        px[k] = x; py[k] = y; pz[k] = z;
        hp[k] = 0.5f * fmaf(x, x, fmaf(y, y, z * z));
        rmin[k] = __int_as_float(INF_BITS);
    }
    __syncthreads();

    // j groups of 32: lane processes j = jg + ((lane+n)&31) at inner step n.
    // The col-min `cm` travels with its j via one shfl per step; after 32 steps
    // each j's cm has accumulated all 256 i's of the warp and sits on lane j-jg.
    for (int jg = 0; jg < JT; jg += 32) {
        float cm = __int_as_float(INF_BITS);
#pragma unroll 4
        for (int n = 0; n < 32; n++) {
            float4 q = sq[jg + ((lane + n) & 31)];   // conflict-free LDS.128
            float t[IPT];
#pragma unroll
            for (int k = 0; k < IPT; k++) {
                float u = fmaf(pz[k], q.z, fmaf(py[k], q.y, fmaf(px[k], q.x, q.w)));
                t[k] = fmaf(u, -1.0f, hp[k]);        // FFMA-imm: dist^2/2
                rmin[k] = fminf(rmin[k], t[k]);      // row mins (alu pipe)
            }
            float tm = fminf(fminf(fminf(t[0], t[1]), fminf(t[2], t[3])),
                             fminf(fminf(t[4], t[5]), fminf(t[6], t[7])));
            cm = fminf(cm, tm);
            cm = __shfl_sync(0xffffffffu, cm, lane + 1);   // pass cm along with its j
        }
        scol[w][jg + lane] = cm;
    }

    // Row partials -> global atomic min (int-ordered, values >= 0).
    int* grow = &g_rmin[b * NPTS];
#pragma unroll
    for (int k = 0; k < IPT; k++)
        atomicMin(&grow[ib + k], __float_as_int(rmin[k]));

    __syncthreads();
    // Combine 4 warps' col mins; col partials -> global atomic min.
    int* gcol = &g_cmin[b * NPTS];
    for (int j = tid; j < JT; j += THREADS) {
        float m = fminf(fminf(scol[0][j], scol[1][j]), fminf(scol[2][j], scol[3][j]));
        atomicMin(&gcol[jch * JT + j], __float_as_int(m));
    }
}

// Reset min arrays to +inf and zero the output scalar.
__global__ void chamfer_init_kernel(float* __restrict__ out) {
    int idx = blockIdx.x * blockDim.x + threadIdx.x;   // 8192 threads
    int4 v = make_int4(INF_BITS, INF_BITS, INF_BITS, INF_BITS);
    reinterpret_cast<int4*>(g_rmin)[idx] = v;
    reinterpret_cast<int4*>(g_cmin)[idx] = v;
    if (idx == 0) *out = 0.0f;
}

// Sum both directions' mins, mean, accumulate scalar.
__global__ void chamfer_tail_kernel(float* __restrict__ out) {
    __shared__ float red[256];
    const int b    = blockIdx.x;
    const int side = blockIdx.y;
    const int* base = (side == 0 ? g_rmin : g_cmin) + b * NPTS;
    float sum = 0.0f;
    for (int i = threadIdx.x; i < NPTS; i += 256)
        sum += __int_as_float(base[i]);
    red[threadIdx.x] = sum;
    __syncthreads();
    for (int o = 128; o; o >>= 1) {
        if (threadIdx.x < o) red[threadIdx.x] += red[threadIdx.x + o];
        __syncthreads();
    }
    // stored values are dist^2/2 -> x2; mean over NB batches and NPTS points.
    if (threadIdx.x == 0)
        atomicAdd(out, red[0] * (2.0f / ((float)NB * (float)NPTS)));
}

extern "C" void kernel_launch(void* const* d_in, const int* in_sizes, int n_in,
                              void* d_out, int out_size) {
    const float* pred = (const float*)d_in[0];
    const float* tgt  = (const float*)d_in[1];
    float* out = (float*)d_out;
    (void)in_sizes; (void)n_in; (void)out_size;

    chamfer_init_kernel<<<32, 256>>>(out);          // 8192 threads x int4 per array
    dim3 grid(JCH, ICH, NB);                        // 16 x 8 x 4 = 512 CTAs
    chamfer_cross_kernel<<<grid, THREADS>>>(pred, tgt);
    dim3 tgrid(NB, 2);
    chamfer_tail_kernel<<<tgrid, 256>>>(out);
}

// round 10
// speedup vs baseline: 1.6008x; 1.0385x over previous
#include <cuda_runtime.h>
#include <cstdint>

// Fixed shapes: pred/target = [4, 8192, 3] fp32
#define NB        4
#define NPTS      8192
#define THREADS   128
#define IPT       8                    // pred points per thread
#define I_PER_CTA 1024                 // 4 warps * 32 lanes * IPT
#define ICH       8                    // 8192 / 1024
#define JT        64                   // targets per tile
#define JCH       (NPTS / JT)          // 128 tiles per (b, ich)
#define NCOMBO    (NB * ICH)           // 32 (b, ich) combos
#define GRID      888                  // 148 SMs * 6 CTAs = one uniform wave
#define INF_BITS  0x7f800000

// Global mins as int bits (dist^2/2 >= 0 -> IEEE order == int order).
__device__ int          g_rmin[NB * NPTS];
__device__ int          g_cmin[NB * NPTS];
__device__ unsigned int g_next[NCOMBO];   // per-combo j-tile work queues
__device__ unsigned int g_done;

__global__ void chamfer_init_kernel() {
    int idx = blockIdx.x * blockDim.x + threadIdx.x;   // 8192 threads
    int4 v = make_int4(INF_BITS, INF_BITS, INF_BITS, INF_BITS);
    reinterpret_cast<int4*>(g_rmin)[idx] = v;
    reinterpret_cast<int4*>(g_cmin)[idx] = v;
    if (idx < NCOMBO) g_next[idx] = 0u;
    if (idx == 0) g_done = 0u;
}

// Persistent symmetric cross kernel. Each (i,j) computed ONCE:
//   t = h_p + h_q - p.q = dist^2/2   (3 FFMA + 1 FFMA-imm)
// Row mins live in registers for the CTA's whole lifetime (fixed i-range);
// column mins via systolic rotation (1 SHFL per 256 pairs).
__global__ void __launch_bounds__(THREADS, 6)
chamfer_cross_kernel(const float* __restrict__ pred, const float* __restrict__ tgt,
                     float* __restrict__ out) {
    __shared__ float4       sq[JT];        // (qx, qy, qz, -h_q)
    __shared__ float        scol[4][JT];   // per-warp col mins
    __shared__ unsigned int s_tile;
    __shared__ int          s_last;
    __shared__ float        s_red[THREADS];

    const int combo = blockIdx.x & (NCOMBO - 1);   // 888 CTAs -> 27-28 per combo
    const int b     = combo >> 3;
    const int ich   = combo & 7;
    const int tid   = threadIdx.x;
    const int w     = tid >> 5;
    const int lane  = tid & 31;

    const float* P = pred + (size_t)b * NPTS * 3;
    const float* Q = tgt  + (size_t)b * NPTS * 3;

    // Register-resident pred points for this lane (fixed for whole kernel).
    const int ib = ich * I_PER_CTA + w * (32 * IPT) + lane * IPT;
    float px[IPT], py[IPT], pz[IPT], hp[IPT], rmin[IPT];
#pragma unroll
    for (int k = 0; k < IPT; k++) {
        float x = P[3 * (ib + k) + 0];
        float y = P[3 * (ib + k) + 1];
        float z = P[3 * (ib + k) + 2];
        px[k] = x; py[k] = y; pz[k] = z;
        hp[k] = 0.5f * fmaf(x, x, fmaf(y, y, z * z));
        rmin[k] = __int_as_float(INF_BITS);
    }

    int* grow = &g_rmin[b * NPTS];
    int* gcol = &g_cmin[b * NPTS];

    for (;;) {
        if (tid == 0) s_tile = atomicAdd(&g_next[combo], 1u);
        __syncthreads();                       // also protects sq/scol reuse
        const unsigned int jch = s_tile;
        if (jch >= JCH) break;

        // Stage this j-tile.
        if (tid < JT) {
            int gj = jch * JT + tid;
            float x = Q[3 * gj + 0], y = Q[3 * gj + 1], z = Q[3 * gj + 2];
            float nh = -0.5f * fmaf(x, x, fmaf(y, y, z * z));
            sq[tid] = make_float4(x, y, z, nh);
        }
        __syncthreads();

        // Systolic: lane handles j = jg + ((lane+n)&31) at step n; col-min
        // rides one SHFL per step and lands back on its home lane.
#pragma unroll
        for (int jg = 0; jg < JT; jg += 32) {
            float cm = __int_as_float(INF_BITS);
#pragma unroll 4
            for (int n = 0; n < 32; n++) {
                float4 q = sq[jg + ((lane + n) & 31)];   // conflict-free LDS.128
                float t[IPT];
#pragma unroll
                for (int k = 0; k < IPT; k++) {
                    float u = fmaf(pz[k], q.z, fmaf(py[k], q.y, fmaf(px[k], q.x, q.w)));
                    t[k] = fmaf(u, -1.0f, hp[k]);        // FFMA-imm: dist^2/2
                    rmin[k] = fminf(rmin[k], t[k]);
                }
                float tm = fminf(fminf(fminf(t[0], t[1]), fminf(t[2], t[3])),
                                 fminf(fminf(t[4], t[5]), fminf(t[6], t[7])));
                cm = fminf(cm, tm);
                cm = __shfl_sync(0xffffffffu, cm, lane + 1);
            }
            scol[w][jg + lane] = cm;
        }
        __syncthreads();

        // Combine 4 warps' col mins -> global atomic min.
        if (tid < JT) {
            float m = fminf(fminf(scol[0][tid], scol[1][tid]),
                            fminf(scol[2][tid], scol[3][tid]));
            atomicMin(&gcol[jch * JT + tid], __float_as_int(m));
        }
    }

    // Flush register row mins once per CTA.
#pragma unroll
    for (int k = 0; k < IPT; k++)
        atomicMin(&grow[ib + k], __float_as_int(rmin[k]));

    // Last CTA reduces everything to the scalar output.
    __threadfence();
    if (tid == 0) s_last = (atomicAdd(&g_done, 1u) == GRID - 1);
    __syncthreads();
    if (!s_last) return;
    __threadfence();

    float sum = 0.0f;
    for (int i = tid; i < NB * NPTS; i += THREADS)
        sum += __int_as_float(g_rmin[i]) + __int_as_float(g_cmin[i]);
    s_red[tid] = sum;
    __syncthreads();
    for (int o = THREADS / 2; o; o >>= 1) {
        if (tid < o) s_red[tid] += s_red[tid + o];
        __syncthreads();
    }
    // values are dist^2/2 -> x2; mean over NB batches and NPTS points.
    if (tid == 0)
        *out = s_red[0] * (2.0f / ((float)NB * (float)NPTS));
}

extern "C" void kernel_launch(void* const* d_in, const int* in_sizes, int n_in,
                              void* d_out, int out_size) {
    const float* pred = (const float*)d_in[0];
    const float* tgt  = (const float*)d_in[1];
    float* out = (float*)d_out;
    (void)in_sizes; (void)n_in; (void)out_size;

    chamfer_init_kernel<<<32, 256>>>();                    // 8192 threads
    chamfer_cross_kernel<<<GRID, THREADS>>>(pred, tgt, out);
}

// round 12
// speedup vs baseline: 1.6425x; 1.0261x over previous
#include <cuda_runtime.h>
#include <cstdint>

// Fixed shapes: pred/target = [4, 8192, 3] fp32
#define NB        4
#define NPTS      8192
#define THREADS   128
#define IPT       8                    // pred points per thread
#define I_PER_CTA 1024                 // 4 warps * 32 lanes * IPT
#define ICH       8                    // 8192 / 1024
#define JT        64                   // targets per tile
#define JCH       (NPTS / JT)          // 128 tiles per (b, ich)
#define NCOMBO    (NB * ICH)           // 32 (b, ich) combos
#define OCC       8
#define GRID      (148 * OCC)          // 1184: one uniform wave at 8 CTAs/SM
#define INF_BITS  0x7f800000

// Global mins as int bits (values >= 0 -> IEEE order == int order).
__device__ int          g_rmin[NB * NPTS];
__device__ int          g_cmin[NB * NPTS];
__device__ unsigned int g_next[NCOMBO];   // per-combo j-tile work queues
__device__ unsigned int g_done;

__global__ void chamfer_init_kernel() {
    int idx = blockIdx.x * blockDim.x + threadIdx.x;   // 8192 threads
    int4 v = make_int4(INF_BITS, INF_BITS, INF_BITS, INF_BITS);
    reinterpret_cast<int4*>(g_rmin)[idx] = v;
    reinterpret_cast<int4*>(g_cmin)[idx] = v;
    if (idx < NCOMBO) g_next[idx] = 0u;
    if (idx == 0) g_done = 0u;
}

// Persistent symmetric cross kernel. Each (i,j) computed ONCE:
//   s = h_q - p.q   (3 FFMA with negated-p source modifiers, q.w = +h_q)
//   rows: min(s), h_p added once at flush;  cols: t = h_p + s (FFMA-imm),
//   8-way tree, then systolic SHFL ride (1 SHFL per 256 pairs).
__global__ void __launch_bounds__(THREADS, OCC)
chamfer_cross_kernel(const float* __restrict__ pred, const float* __restrict__ tgt,
                     float* __restrict__ out) {
    // Duplicated tile halves for linear (wrap-free) systolic reads:
    //   sq[h][m] = q-tile element h*32 + (m & 31), m in [0, 63)
    __shared__ float4       sq[2][63];
    __shared__ float        scol[4][JT];   // per-warp col mins
    __shared__ unsigned int s_tile;
    __shared__ int          s_last;
    __shared__ float        s_red[THREADS];

    const int combo = blockIdx.x & (NCOMBO - 1);
    const int b     = combo >> 3;
    const int ich   = combo & 7;
    const int tid   = threadIdx.x;
    const int w     = tid >> 5;
    const int lane  = tid & 31;

    const float* P = pred + (size_t)b * NPTS * 3;
    const float* Q = tgt  + (size_t)b * NPTS * 3;

    // Register-resident pred points for this lane (fixed for whole kernel).
    const int ib = ich * I_PER_CTA + w * (32 * IPT) + lane * IPT;
    float px[IPT], py[IPT], pz[IPT], hp[IPT], smin[IPT];
#pragma unroll
    for (int k = 0; k < IPT; k++) {
        float x = P[3 * (ib + k) + 0];
        float y = P[3 * (ib + k) + 1];
        float z = P[3 * (ib + k) + 2];
        px[k] = x; py[k] = y; pz[k] = z;
        hp[k] = 0.5f * fmaf(x, x, fmaf(y, y, z * z));
        smin[k] = __int_as_float(INF_BITS);
    }

    int* grow = &g_rmin[b * NPTS];
    int* gcol = &g_cmin[b * NPTS];

    for (;;) {
        if (tid == 0) s_tile = atomicAdd(&g_next[combo], 1u);
        __syncthreads();                       // also protects sq/scol reuse
        const unsigned int jch = s_tile;
        if (jch >= JCH) break;

        // Stage this j-tile into duplicated halves.  q.w = +h_q.
        if (tid < JT) {
            int gj = jch * JT + tid;
            float x = Q[3 * gj + 0], y = Q[3 * gj + 1], z = Q[3 * gj + 2];
            float ph = 0.5f * fmaf(x, x, fmaf(y, y, z * z));
            int h = tid >> 5, m = tid & 31;
            float4 v = make_float4(x, y, z, ph);
            sq[h][m] = v;
            if (m < 31) sq[h][32 + m] = v;
        }
        __syncthreads();

        // Systolic: lane reads sq[h][lane+n] (linear, conflict-free); the
        // col-min rides one SHFL per step and lands back on its home lane.
#pragma unroll
        for (int h = 0; h < 2; h++) {
            const float4* qp = &sq[h][lane];
            float cm = __int_as_float(INF_BITS);
#pragma unroll 8
            for (int n = 0; n < 32; n++) {
                float4 q = qp[n];                        // LDS.128, ptr bump only
                float tm;
#pragma unroll
                for (int k = 0; k < IPT; k += 2) {
                    // s = h_q - p.q  (negations fold into FFMA source modifiers)
                    float s0 = fmaf(-pz[k],     q.z, fmaf(-py[k],     q.y, fmaf(-px[k],     q.x, q.w)));
                    float s1 = fmaf(-pz[k + 1], q.z, fmaf(-py[k + 1], q.y, fmaf(-px[k + 1], q.x, q.w)));
                    smin[k]     = fminf(smin[k],     s0);   // rows: s only
                    smin[k + 1] = fminf(smin[k + 1], s1);
                    float t0 = fmaf(s0, 1.0f, hp[k]);       // t = hp + s (FFMA-imm)
                    float t1 = fmaf(s1, 1.0f, hp[k + 1]);
                    float tp = fminf(t0, t1);
                    tm = (k == 0) ? tp : fminf(tm, tp);
                }
                cm = fminf(cm, tm);
                cm = __shfl_sync(0xffffffffu, cm, lane + 1);
            }
            scol[w][h * 32 + lane] = cm;
        }
        __syncthreads();

        // Combine 4 warps' col mins -> global atomic min.
        if (tid < JT) {
            float m = fminf(fminf(scol[0][tid], scol[1][tid]),
                            fminf(scol[2][tid], scol[3][tid]));
            atomicMin(&gcol[jch * JT + tid], __float_as_int(m));
        }
    }

    // Flush register row mins once per CTA (add hp back here).
#pragma unroll
    for (int k = 0; k < IPT; k++)
        atomicMin(&grow[ib + k], __float_as_int(hp[k] + smin[k]));

    // Last CTA reduces everything to the scalar output.
    __threadfence();
    if (tid == 0) s_last = (atomicAdd(&g_done, 1u) == GRID - 1);
    __syncthreads();
    if (!s_last) return;
    __threadfence();

    float sum = 0.0f;
    for (int i = tid; i < NB * NPTS; i += THREADS)
        sum += __int_as_float(g_rmin[i]) + __int_as_float(g_cmin[i]);
    s_red[tid] = sum;
    __syncthreads();
    for (int o = THREADS / 2; o; o >>= 1) {
        if (tid < o) s_red[tid] += s_red[tid + o];
        __syncthreads();
    }
    // values are dist^2/2 -> x2; mean over NB batches and NPTS points.
    if (tid == 0)
        *out = s_red[0] * (2.0f / ((float)NB * (float)NPTS));
}

extern "C" void kernel_launch(void* const* d_in, const int* in_sizes, int n_in,
                              void* d_out, int out_size) {
    const float* pred = (const float*)d_in[0];
    const float* tgt  = (const float*)d_in[1];
    float* out = (float*)d_out;
    (void)in_sizes; (void)n_in; (void)out_size;

    chamfer_init_kernel<<<32, 256>>>();
    chamfer_cross_kernel<<<GRID, THREADS>>>(pred, tgt, out);
}